// round 8
// baseline (speedup 1.0000x reference)
#include <cuda_runtime.h>
#include <cuda_bf16.h>
#include <cstdint>

// ============================================================================
// HopfieldNetwork, exact int8 tensor cores + per-row attractor tracking.
//
// Exactness: W integer [-64,64] symmetric, x in {-1,0,1}; y=x@W exact s32;
// E = x.y exact int; |dE|<1e-6 === integer equality.
//
// Row dynamics are independent: y[r]=x[r]@W. Synchronous symmetric Hopfield
// rows end in fixed points (x_{m+1}==x_m) or 2-cycles (x_{m+1}==x_{m-1});
// after detection the row's states/energies are exactly periodic (period<=2):
//  - x ring of 3: copyx(m) sets slot (m+1)%3 := slot (m-1)%3 for inactive
//    rows (correct for fixed and 2-cycle by induction).
//  - E parity buffers E[0],E[1]: 2-cycle rows need nothing (parity aligns);
//    newly/perm fixed rows get E[m&1] := E[(m-1)&1] in compact(m).
// Step m runs the GEMM only on compacted active rows; epilogue detects
// fixed/cycle via exact byte compares (atomicAnd on per-row flags).
// ============================================================================

#define BATCH 8192
#define NF 1024
#define BM 128
#define BN 128
#define BK 64
#define PR 80      // padded row stride in bytes (20 banks: conflict-free ldmatrix)
#define NSTG 4
#define A_STG (BM * PR)
#define B_BASE (NSTG * A_STG)
#define SMEM_TOTAL (2 * NSTG * A_STG)   // 81920

__device__ int8_t g_x[3][BATCH * NF];   // state ring (8 MB each)
__device__ int8_t g_w[NF * NF];         // W as int8 (symmetric)
__device__ int g_E[2][BATCH];           // exact integer energies by parity
__device__ int g_flags[BATCH];          // bit0: ==x_m (fixed), bit1: ==x_{m-1} (cycle)
__device__ unsigned char g_activeB[BATCH];
__device__ int g_idx[BATCH];            // compacted active rows (padded to 128)
__device__ int g_nact;
__device__ int g_finished;
__device__ int g_result;

__device__ __forceinline__ int8_t sgn8(int v) {
    return (int8_t)((v > 0) - (v < 0));
}

// ----------------------------------------------------------------------------
__global__ void init_kernel(const int* __restrict__ max_iter) {
    if (blockIdx.x == 0 && threadIdx.x == 0) {
        g_result = 0;
        g_finished = (*max_iter <= 0) ? 1 : 0;
    }
}

__global__ void cvt_w_kernel(const float* __restrict__ w) {
    int i = (blockIdx.x * blockDim.x + threadIdx.x) * 4;
    float4 v = *(const float4*)(w + i);
    char4 o;
    o.x = (int8_t)__float2int_rn(v.x);
    o.y = (int8_t)__float2int_rn(v.y);
    o.z = (int8_t)__float2int_rn(v.z);
    o.w = (int8_t)__float2int_rn(v.w);
    *(char4*)(g_w + i) = o;
}

__global__ void cvt_x_kernel(const float* __restrict__ x) {
    int i = (blockIdx.x * blockDim.x + threadIdx.x) * 4;
    float4 v = *(const float4*)(x + i);
    char4 o;
    o.x = (int8_t)__float2int_rn(v.x);
    o.y = (int8_t)__float2int_rn(v.y);
    o.z = (int8_t)__float2int_rn(v.z);
    o.w = (int8_t)__float2int_rn(v.w);
    *(char4*)(&g_x[0][0] + i) = o;
}

// ----------------------------------------------------------------------------
// compact(m): build active list for step m from flags set by step m-1.
// Kept rows: zero E[m&1], reset flags=3, mark active. Dropped-fixed rows:
// E[m&1] := E[(m-1)&1] (2-cycle rows' parities already align).
// ----------------------------------------------------------------------------
__global__ void compact_kernel(int m, const int* __restrict__ max_iter) {
    if (g_finished || m > *max_iter) return;
    __shared__ int s_cnt;
    if (threadIdx.x == 0) s_cnt = 0;
    __syncthreads();
    for (int r = threadIdx.x; r < BATCH; r += blockDim.x) {
        bool keep = (m == 0) ? true : (g_flags[r] == 0);
        if (keep) {
            int p = atomicAdd(&s_cnt, 1);
            g_idx[p] = r;
            g_flags[r] = 3;
            g_activeB[r] = 1;
            g_E[m & 1][r] = 0;
        } else {
            g_activeB[r] = 0;
            if (g_flags[r] & 1) g_E[m & 1][r] = g_E[(m - 1) & 1][r];
        }
    }
    __syncthreads();
    if (threadIdx.x == 0) {
        int n = s_cnt;
        g_nact = n;
        int pad = (128 - (n & 127)) & 127;
        for (int i = 0; i < pad; i++) g_idx[n + i] = (n > 0) ? g_idx[0] : 0;
    }
}

// ----------------------------------------------------------------------------
// copyx(m): x[(m+1)%3][r] := x[(m-1)%3][r] for INACTIVE rows (periodic cont.).
// ----------------------------------------------------------------------------
__global__ void copyx_kernel(int m, const int* __restrict__ max_iter) {
    if (g_finished || m == 0 || m > *max_iter) return;
    const int8_t* src = g_x[(m + 2) % 3];   // (m-1)%3
    int8_t* dst = g_x[(m + 1) % 3];
    int stride = gridDim.x * blockDim.x;
    for (int c = blockIdx.x * blockDim.x + threadIdx.x; c < BATCH * NF / 16; c += stride) {
        int row = c >> 6;                   // 16B chunks, NF/16 = 64 per row
        if (g_activeB[row]) continue;
        ((int4*)dst)[c] = ((const int4*)src)[c];
    }
}

// ----------------------------------------------------------------------------
// Step kernel: fused s8 GEMM on compacted rows + sign + energy + detection.
// grid = (8, 64), 256 threads (8 warps, 2x4 -> 64x32 per warp).
// ----------------------------------------------------------------------------
__global__ __launch_bounds__(256) void step_kernel(int m, const int* __restrict__ max_iter) {
    if (g_finished || m > *max_iter) return;
    const int nact = g_nact;
    const int byBase = blockIdx.y * BM;
    if (byBase >= nact) return;

    const int8_t* __restrict__ xcur = g_x[m % 3];
    int8_t* __restrict__ xnext = g_x[(m + 1) % 3];
    const int8_t* __restrict__ xprev = g_x[(m + 2) % 3];   // x_{m-1}
    int* __restrict__ E = g_E[m & 1];

    extern __shared__ __align__(128) int8_t smem[];
    int8_t* As = smem;
    int8_t* Bs = smem + B_BASE;
    __shared__ int s_idx[BM];

    const int tid = threadIdx.x;
    const int lane = tid & 31, warp = tid >> 5;
    const int warpM = warp & 1, warpN = warp >> 1;
    const int colBase = blockIdx.x * BN;

    if (tid < BM) s_idx[tid] = g_idx[byBase + tid];
    __syncthreads();

    int acc[4][4][4];
#pragma unroll
    for (int a = 0; a < 4; a++)
#pragma unroll
        for (int b = 0; b < 4; b++)
#pragma unroll
            for (int c = 0; c < 4; c++) acc[a][b][c] = 0;

    const int ldRow = tid >> 2;
    const int ldOff = (tid & 3) * 16;
    auto loadStage = [&](int buf, int kt) {
#pragma unroll
        for (int rep = 0; rep < 2; rep++) {
            int row = ldRow + rep * 64;
            uint32_t dst = (uint32_t)__cvta_generic_to_shared(
                &As[buf * A_STG + row * PR + ldOff]);
            const int8_t* src = xcur + (size_t)s_idx[row] * NF + kt * BK + ldOff;
            asm volatile("cp.async.cg.shared.global [%0], [%1], 16;\n" :: "r"(dst), "l"(src));
        }
#pragma unroll
        for (int rep = 0; rep < 2; rep++) {
            int row = ldRow + rep * 64;
            uint32_t dst = (uint32_t)__cvta_generic_to_shared(
                &Bs[buf * A_STG + row * PR + ldOff]);
            const int8_t* src = g_w + (size_t)(colBase + row) * NF + kt * BK + ldOff;
            asm volatile("cp.async.cg.shared.global [%0], [%1], 16;\n" :: "r"(dst), "l"(src));
        }
    };

#pragma unroll
    for (int s = 0; s < NSTG - 1; s++) {
        loadStage(s, s);
        asm volatile("cp.async.commit_group;\n");
    }

    const int lr8 = lane & 7;
    const int seg8 = (lane >> 3) & 1;
    const int kh16 = (lane >> 4) & 1;

    const int KT = NF / BK;  // 16
#pragma unroll 1
    for (int kt = 0; kt < KT; kt++) {
        int buf = kt & (NSTG - 1);
        asm volatile("cp.async.wait_group %0;\n" :: "n"(NSTG - 2));
        __syncthreads();

        int ktn = kt + NSTG - 1;
        if (ktn < KT) loadStage(ktn & (NSTG - 1), ktn);
        asm volatile("cp.async.commit_group;\n");

#pragma unroll
        for (int ks = 0; ks < 2; ks++) {
            const int kbyte = ks * 32;
            uint32_t af[4][4];
            uint32_t bf[2][4];
#pragma unroll
            for (int mi = 0; mi < 4; mi++) {
                int row = warpM * 64 + mi * 16 + lr8 + seg8 * 8;
                uint32_t addr = (uint32_t)__cvta_generic_to_shared(
                    &As[buf * A_STG + row * PR + kbyte + kh16 * 16]);
                asm volatile("ldmatrix.sync.aligned.m8n8.x4.shared.b16 {%0,%1,%2,%3}, [%4];"
                             : "=r"(af[mi][0]), "=r"(af[mi][1]), "=r"(af[mi][2]), "=r"(af[mi][3])
                             : "r"(addr));
            }
#pragma unroll
            for (int np = 0; np < 2; np++) {
                int row = warpN * 32 + np * 16 + lr8 + seg8 * 8;
                uint32_t addr = (uint32_t)__cvta_generic_to_shared(
                    &Bs[buf * A_STG + row * PR + kbyte + kh16 * 16]);
                asm volatile("ldmatrix.sync.aligned.m8n8.x4.shared.b16 {%0,%1,%2,%3}, [%4];"
                             : "=r"(bf[np][0]), "=r"(bf[np][1]), "=r"(bf[np][2]), "=r"(bf[np][3])
                             : "r"(addr));
            }
#pragma unroll
            for (int mi = 0; mi < 4; mi++)
#pragma unroll
                for (int ni = 0; ni < 4; ni++) {
                    int np = ni >> 1, lh = ni & 1;
                    asm volatile(
                        "mma.sync.aligned.m16n8k32.row.col.s32.s8.s8.s32 "
                        "{%0,%1,%2,%3}, {%4,%5,%6,%7}, {%8,%9}, {%0,%1,%2,%3};"
                        : "+r"(acc[mi][ni][0]), "+r"(acc[mi][ni][1]),
                          "+r"(acc[mi][ni][2]), "+r"(acc[mi][ni][3])
                        : "r"(af[mi][0]), "r"(af[mi][1]), "r"(af[mi][2]), "r"(af[mi][3]),
                          "r"(bf[np][lh]), "r"(bf[np][lh + 2]));
                }
        }
    }

    // ---- Epilogue: sign -> x_next, energy, fixed/2-cycle detection ----
    const int lr = lane >> 2, lc = lane & 3;
#pragma unroll
    for (int mi = 0; mi < 4; mi++) {
        int l0 = warpM * 64 + mi * 16 + lr;
        int l1 = l0 + 8;
        int gr0 = s_idx[l0], gr1 = s_idx[l1];
        bool v0 = (byBase + l0) < nact;
        bool v1 = (byBase + l1) < nact;
        int s0 = 0, s1 = 0;
        bool f0 = true, c0 = true, f1 = true, c1 = true;
#pragma unroll
        for (int ni = 0; ni < 4; ni++) {
            int c = colBase + warpN * 32 + ni * 8 + lc * 2;
            int w0 = acc[mi][ni][0], w1 = acc[mi][ni][1];
            int w2 = acc[mi][ni][2], w3 = acc[mi][ni][3];
            char2 xa = *(const char2*)(xcur + (size_t)gr0 * NF + c);
            char2 xb = *(const char2*)(xcur + (size_t)gr1 * NF + c);
            s0 += (int)xa.x * w0 + (int)xa.y * w1;
            s1 += (int)xb.x * w2 + (int)xb.y * w3;
            char2 o0; o0.x = sgn8(w0); o0.y = sgn8(w1);
            char2 o1; o1.x = sgn8(w2); o1.y = sgn8(w3);
            unsigned short n0 = *(unsigned short*)&o0;
            unsigned short n1 = *(unsigned short*)&o1;
            f0 &= (n0 == *(const unsigned short*)&xa);
            f1 &= (n1 == *(const unsigned short*)&xb);
            unsigned short p0 = *(const unsigned short*)(xprev + (size_t)gr0 * NF + c);
            unsigned short p1 = *(const unsigned short*)(xprev + (size_t)gr1 * NF + c);
            c0 &= (n0 == p0);
            c1 &= (n1 == p1);
            if (v0) *(char2*)(xnext + (size_t)gr0 * NF + c) = o0;
            if (v1) *(char2*)(xnext + (size_t)gr1 * NF + c) = o1;
        }
        if (m == 0) { c0 = false; c1 = false; }   // no x_{-1}
        int mask = (f0 ? 1 : 0) | (c0 ? 2 : 0) | ((f1 ? 1 : 0) | (c1 ? 2 : 0)) << 2;
        mask &= __shfl_xor_sync(0xffffffffu, mask, 1);
        mask &= __shfl_xor_sync(0xffffffffu, mask, 2);
        s0 += __shfl_xor_sync(0xffffffffu, s0, 1);
        s0 += __shfl_xor_sync(0xffffffffu, s0, 2);
        s1 += __shfl_xor_sync(0xffffffffu, s1, 1);
        s1 += __shfl_xor_sync(0xffffffffu, s1, 2);
        if (lc == 0) {
            if (v0) {
                atomicAdd(&E[gr0], s0);
                atomicAnd(&g_flags[gr0], mask & 3);
            }
            if (v1) {
                atomicAdd(&E[gr1], s1);
                atomicAnd(&g_flags[gr1], (mask >> 2) & 3);
            }
        }
    }
}

// ----------------------------------------------------------------------------
// check(i): after step i+1. Exact integer-energy convergence test, all rows.
// ----------------------------------------------------------------------------
__global__ void check_kernel(int i, const int* __restrict__ max_iter) {
    int mit = *max_iter;
    if (g_finished || i >= mit) return;
    const int* Ea = g_E[i & 1];
    const int* Eb = g_E[(i + 1) & 1];
    __shared__ int s_bad;
    if (threadIdx.x == 0) s_bad = 0;
    __syncthreads();
    int bad = 0;
    for (int r = threadIdx.x; r < BATCH; r += blockDim.x)
        if (Ea[r] != Eb[r]) bad = 1;
    if (bad) s_bad = 1;
    __syncthreads();
    if (threadIdx.x == 0) {
        if (!s_bad) {
            g_finished = 1;
            g_result = i % 3;          // converged: keep OLD x_i
        } else if (i == mit - 1) {
            g_finished = 1;
            g_result = (i + 1) % 3;    // iteration cap
        }
    }
}

__global__ void out_kernel(float* __restrict__ out) {
    const int8_t* src = g_x[g_result];
    size_t i = ((size_t)blockIdx.x * blockDim.x + threadIdx.x) * 4;
    char4 v = *(const char4*)(src + i);
    float4 o;
    o.x = (float)v.x; o.y = (float)v.y; o.z = (float)v.z; o.w = (float)v.w;
    *(float4*)(out + i) = o;
}

// ----------------------------------------------------------------------------
extern "C" void kernel_launch(void* const* d_in, const int* in_sizes, int n_in,
                              void* d_out, int out_size) {
    const float* x = (const float*)d_in[0];
    const float* w = (const float*)d_in[1];
    const int* maxit = (const int*)d_in[2];
    float* out = (float*)d_out;

    cudaFuncSetAttribute(step_kernel, cudaFuncAttributeMaxDynamicSharedMemorySize,
                         SMEM_TOTAL);

    init_kernel<<<1, 32>>>(maxit);
    cvt_w_kernel<<<NF * NF / (256 * 4), 256>>>(w);
    cvt_x_kernel<<<BATCH * NF / (256 * 4), 256>>>(x);

    dim3 grid(NF / BN, BATCH / BM);  // (8, 64); y gated by g_nact on device
    for (int mstep = 0; mstep <= 30; mstep++) {
        compact_kernel<<<1, 1024>>>(mstep, maxit);
        copyx_kernel<<<512, 256>>>(mstep, maxit);
        step_kernel<<<grid, 256, SMEM_TOTAL>>>(mstep, maxit);
        if (mstep >= 1) check_kernel<<<1, 256>>>(mstep - 1, maxit);
    }
    out_kernel<<<BATCH * NF / (4 * 256), 256>>>(out);
}

// round 9
// speedup vs baseline: 1.1794x; 1.1794x over previous
#include <cuda_runtime.h>
#include <cuda_bf16.h>
#include <cstdint>

// ============================================================================
// HopfieldNetwork, exact int8 tensor-core formulation (sm_100-portable PTX).
//
//  - W = P^T P - diag(...): integer in [-64,64], SYMMETRIC (so B = W^T = W)
//  - x in {-1,0,+1}
//  - y = x @ W : |y| <= 2^16 -> exact in s32
//  - E = -0.5 * x.y exact    -> |dE|<1e-6 === integer equality
//
// Round 8: dense schedule (round-5), tiles shrunk to 64x128 -> 1024 tiles over
// 148 SMs (busiest 7 vs mean 6.92) to remove the ~15% integral-tile tail that
// binds under the legacy-IMMA per-SM saturation ceiling.
// ============================================================================

#define BATCH 8192
#define NF 1024
#define BM 64
#define BN 128
#define BK 64
#define PR 80      // padded row stride in bytes (20 banks: conflict-free ldmatrix)
#define NSTG 4
#define A_STG (BM * PR)                 // 5120
#define B_STG (BN * PR)                 // 10240
#define B_BASE (NSTG * A_STG)
#define SMEM_TOTAL (NSTG * (A_STG + B_STG))   // 61440

__device__ int8_t g_x[3][BATCH * NF];   // state ring (8 MB each)
__device__ int8_t g_w[NF * NF];         // W as int8 (symmetric)
__device__ int g_E[2][BATCH];           // exact integer energies (x . y)
__device__ int g_finished;
__device__ int g_result;

__device__ __forceinline__ int8_t sgn8(int v) {
    return (int8_t)((v > 0) - (v < 0));
}

// ----------------------------------------------------------------------------
__global__ void init_kernel(const int* __restrict__ max_iter) {
    int idx = blockIdx.x * blockDim.x + threadIdx.x;
    if (idx < 2 * BATCH) ((int*)g_E)[idx] = 0;
    if (idx == 0) {
        g_result = 0;
        g_finished = (*max_iter <= 0) ? 1 : 0;
    }
}

__global__ void cvt_w_kernel(const float* __restrict__ w) {
    int i = (blockIdx.x * blockDim.x + threadIdx.x) * 4;
    float4 v = *(const float4*)(w + i);
    char4 o;
    o.x = (int8_t)__float2int_rn(v.x);
    o.y = (int8_t)__float2int_rn(v.y);
    o.z = (int8_t)__float2int_rn(v.z);
    o.w = (int8_t)__float2int_rn(v.w);
    *(char4*)(g_w + i) = o;
}

__global__ void cvt_x_kernel(const float* __restrict__ x) {
    int i = (blockIdx.x * blockDim.x + threadIdx.x) * 4;
    float4 v = *(const float4*)(x + i);
    char4 o;
    o.x = (int8_t)__float2int_rn(v.x);
    o.y = (int8_t)__float2int_rn(v.y);
    o.z = (int8_t)__float2int_rn(v.z);
    o.w = (int8_t)__float2int_rn(v.w);
    *(char4*)(&g_x[0][0] + i) = o;
}

// ----------------------------------------------------------------------------
// Step kernel: fused s8 GEMM + sign + integer energy.
// grid = (NF/BN, BATCH/BM) = (8, 128) = 1024 CTAs, 256 threads.
// 8 warps as 2(M) x 4(N); each warp owns a 32x32 output tile.
// ----------------------------------------------------------------------------
__global__ __launch_bounds__(256) void step_kernel(int m, const int* __restrict__ max_iter) {
    if (g_finished || m > *max_iter) return;

    const int8_t* __restrict__ xcur = g_x[m % 3];
    int8_t* __restrict__ xnext = g_x[(m + 1) % 3];
    int* __restrict__ E = g_E[m & 1];

    extern __shared__ __align__(128) int8_t smem[];
    int8_t* As = smem;              // NSTG stages of BM*PR
    int8_t* Bs = smem + B_BASE;     // NSTG stages of BN*PR

    const int tid = threadIdx.x;
    const int lane = tid & 31, warp = tid >> 5;
    const int warpM = warp & 1, warpN = warp >> 1;   // 2 x 4 warps, 32x32 tiles
    const int rowBase = blockIdx.y * BM;
    const int colBase = blockIdx.x * BN;

    int acc[2][4][4];
#pragma unroll
    for (int a = 0; a < 2; a++)
#pragma unroll
        for (int b = 0; b < 4; b++)
#pragma unroll
            for (int c = 0; c < 4; c++) acc[a][b][c] = 0;

    // Per-stage: A 64 rows x 64B (256 chunks, 1/thread) +
    //            B 128 rows x 64B (512 chunks, 2/thread).
    const int ldRow = tid >> 2;            // 0..63
    const int ldOff = (tid & 3) * 16;      // 0/16/32/48
    auto loadStage = [&](int buf, int kt) {
        {
            uint32_t dst = (uint32_t)__cvta_generic_to_shared(
                &As[buf * A_STG + ldRow * PR + ldOff]);
            const int8_t* src = xcur + (size_t)(rowBase + ldRow) * NF + kt * BK + ldOff;
            asm volatile("cp.async.cg.shared.global [%0], [%1], 16;\n" :: "r"(dst), "l"(src));
        }
#pragma unroll
        for (int rep = 0; rep < 2; rep++) {
            int row = ldRow + rep * 64;
            uint32_t dst = (uint32_t)__cvta_generic_to_shared(
                &Bs[buf * B_STG + row * PR + ldOff]);
            // B = W^T = W (symmetric): rows are output cols, k contiguous.
            const int8_t* src = g_w + (size_t)(colBase + row) * NF + kt * BK + ldOff;
            asm volatile("cp.async.cg.shared.global [%0], [%1], 16;\n" :: "r"(dst), "l"(src));
        }
    };

    // Prologue: stages 0..NSTG-2 in flight.
#pragma unroll
    for (int s = 0; s < NSTG - 1; s++) {
        loadStage(s, s);
        asm volatile("cp.async.commit_group;\n");
    }

    // ldmatrix lane pattern (A and B identical):
    const int lr8 = lane & 7;
    const int seg8 = (lane >> 3) & 1;
    const int kh16 = (lane >> 4) & 1;

    const int KT = NF / BK;  // 16
#pragma unroll 1
    for (int kt = 0; kt < KT; kt++) {
        int buf = kt & (NSTG - 1);
        asm volatile("cp.async.wait_group %0;\n" :: "n"(NSTG - 2));
        __syncthreads();

        int ktn = kt + NSTG - 1;
        if (ktn < KT) loadStage(ktn & (NSTG - 1), ktn);
        asm volatile("cp.async.commit_group;\n");   // empty commit ok: keeps alignment

#pragma unroll
        for (int ks = 0; ks < 2; ks++) {           // two k32 slices per BK=64
            const int kbyte = ks * 32;
            uint32_t af[2][4];                     // 2 m16 tiles
            uint32_t bf[2][4];                     // 2 n16 pairs (32 cols)
#pragma unroll
            for (int mi = 0; mi < 2; mi++) {
                int row = warpM * 32 + mi * 16 + lr8 + seg8 * 8;
                uint32_t addr = (uint32_t)__cvta_generic_to_shared(
                    &As[buf * A_STG + row * PR + kbyte + kh16 * 16]);
                asm volatile("ldmatrix.sync.aligned.m8n8.x4.shared.b16 {%0,%1,%2,%3}, [%4];"
                             : "=r"(af[mi][0]), "=r"(af[mi][1]), "=r"(af[mi][2]), "=r"(af[mi][3])
                             : "r"(addr));
            }
#pragma unroll
            for (int np = 0; np < 2; np++) {
                int row = warpN * 32 + np * 16 + lr8 + seg8 * 8;
                uint32_t addr = (uint32_t)__cvta_generic_to_shared(
                    &Bs[buf * B_STG + row * PR + kbyte + kh16 * 16]);
                asm volatile("ldmatrix.sync.aligned.m8n8.x4.shared.b16 {%0,%1,%2,%3}, [%4];"
                             : "=r"(bf[np][0]), "=r"(bf[np][1]), "=r"(bf[np][2]), "=r"(bf[np][3])
                             : "r"(addr));
            }
#pragma unroll
            for (int mi = 0; mi < 2; mi++)
#pragma unroll
                for (int ni = 0; ni < 4; ni++) {
                    int np = ni >> 1, lh = ni & 1;
                    asm volatile(
                        "mma.sync.aligned.m16n8k32.row.col.s32.s8.s8.s32 "
                        "{%0,%1,%2,%3}, {%4,%5,%6,%7}, {%8,%9}, {%0,%1,%2,%3};"
                        : "+r"(acc[mi][ni][0]), "+r"(acc[mi][ni][1]),
                          "+r"(acc[mi][ni][2]), "+r"(acc[mi][ni][3])
                        : "r"(af[mi][0]), "r"(af[mi][1]), "r"(af[mi][2]), "r"(af[mi][3]),
                          "r"(bf[np][lh]), "r"(bf[np][lh + 2]));
                }
        }
    }

    // ---- Fused epilogue: x_next = sign(y) (int8), E[row] += x_cur . y ----
    const int lr = lane >> 2, lc = lane & 3;
#pragma unroll
    for (int mi = 0; mi < 2; mi++) {
        int r0 = rowBase + warpM * 32 + mi * 16 + lr;
        int r1 = r0 + 8;
        int s0 = 0, s1 = 0;
#pragma unroll
        for (int ni = 0; ni < 4; ni++) {
            int c = colBase + warpN * 32 + ni * 8 + lc * 2;
            int v0 = acc[mi][ni][0], v1 = acc[mi][ni][1];
            int v2 = acc[mi][ni][2], v3 = acc[mi][ni][3];
            char2 xa = *(const char2*)(xcur + (size_t)r0 * NF + c);
            char2 xb = *(const char2*)(xcur + (size_t)r1 * NF + c);
            s0 += (int)xa.x * v0 + (int)xa.y * v1;
            s1 += (int)xb.x * v2 + (int)xb.y * v3;
            char2 o0; o0.x = sgn8(v0); o0.y = sgn8(v1);
            char2 o1; o1.x = sgn8(v2); o1.y = sgn8(v3);
            *(char2*)(xnext + (size_t)r0 * NF + c) = o0;
            *(char2*)(xnext + (size_t)r1 * NF + c) = o1;
        }
        s0 += __shfl_xor_sync(0xffffffffu, s0, 1);
        s0 += __shfl_xor_sync(0xffffffffu, s0, 2);
        s1 += __shfl_xor_sync(0xffffffffu, s1, 1);
        s1 += __shfl_xor_sync(0xffffffffu, s1, 2);
        if (lc == 0) {
            atomicAdd(&E[r0], s0);
            atomicAdd(&E[r1], s1);
        }
    }
}

// ----------------------------------------------------------------------------
// check(i): runs after step i+1. Exact integer-energy convergence test.
// ----------------------------------------------------------------------------
__global__ void check_kernel(int i, const int* __restrict__ max_iter) {
    int mit = *max_iter;
    if (g_finished || i >= mit) return;
    int* Ea = g_E[i & 1];
    int* Eb = g_E[(i + 1) & 1];
    __shared__ int s_bad;
    if (threadIdx.x == 0) s_bad = 0;
    __syncthreads();
    int bad = 0;
    for (int r = threadIdx.x; r < BATCH; r += blockDim.x) {
        if (Ea[r] != Eb[r]) bad = 1;
        Ea[r] = 0;                     // recycle slot for step i+2
    }
    if (bad) s_bad = 1;
    __syncthreads();
    if (threadIdx.x == 0) {
        if (!s_bad) {
            g_finished = 1;
            g_result = i % 3;          // converged: keep OLD x_i
        } else if (i == mit - 1) {
            g_finished = 1;
            g_result = (i + 1) % 3;    // iteration cap
        }
    }
}

__global__ void out_kernel(float* __restrict__ out) {
    const int8_t* src = g_x[g_result];
    size_t i = ((size_t)blockIdx.x * blockDim.x + threadIdx.x) * 4;
    char4 v = *(const char4*)(src + i);
    float4 o;
    o.x = (float)v.x; o.y = (float)v.y; o.z = (float)v.z; o.w = (float)v.w;
    *(float4*)(out + i) = o;
}

// ----------------------------------------------------------------------------
extern "C" void kernel_launch(void* const* d_in, const int* in_sizes, int n_in,
                              void* d_out, int out_size) {
    const float* x = (const float*)d_in[0];
    const float* w = (const float*)d_in[1];
    const int* maxit = (const int*)d_in[2];
    float* out = (float*)d_out;

    cudaFuncSetAttribute(step_kernel, cudaFuncAttributeMaxDynamicSharedMemorySize,
                         SMEM_TOTAL);

    init_kernel<<<(2 * BATCH + 255) / 256, 256>>>(maxit);
    cvt_w_kernel<<<NF * NF / (256 * 4), 256>>>(w);
    cvt_x_kernel<<<BATCH * NF / (256 * 4), 256>>>(x);

    dim3 grid(NF / BN, BATCH / BM);  // (8, 128) = 1024 CTAs
    for (int mstep = 0; mstep <= 30; mstep++) {
        step_kernel<<<grid, 256, SMEM_TOTAL>>>(mstep, maxit);
        if (mstep >= 1) check_kernel<<<1, 256>>>(mstep - 1, maxit);
    }
    out_kernel<<<BATCH * NF / (4 * 256), 256>>>(out);
}

// round 10
// speedup vs baseline: 1.2746x; 1.0807x over previous
#include <cuda_runtime.h>
#include <cuda_bf16.h>
#include <cstdint>

// ============================================================================
// HopfieldNetwork, exact int8 tensor-core formulation (sm_100-portable PTX).
//
//  - W = P^T P - diag(...): integer in [-64,64], SYMMETRIC (so B = W^T = W)
//  - x in {-1,0,+1}
//  - y = x @ W : |y| <= 2^16 -> exact in s32
//  - E = -0.5 * x.y exact    -> |dE|<1e-6 === integer equality
//
// Round 9: GEMM config frozen (round-8: 64x128 tiles, at the legacy-IMMA
// per-SM ceiling). Convergence check parallelized: 32 blocks, block-OR,
// last-arriving-block decide (was a 1-block serial scan ~3-5us/step).
// ============================================================================

#define BATCH 8192
#define NF 1024
#define BM 64
#define BN 128
#define BK 64
#define PR 80      // padded row stride in bytes (20 banks: conflict-free ldmatrix)
#define NSTG 4
#define A_STG (BM * PR)                 // 5120
#define B_STG (BN * PR)                 // 10240
#define B_BASE (NSTG * A_STG)
#define SMEM_TOTAL (NSTG * (A_STG + B_STG))   // 61440
#define CKBLK 32

__device__ int8_t g_x[3][BATCH * NF];   // state ring (8 MB each)
__device__ int8_t g_w[NF * NF];         // W as int8 (symmetric)
__device__ int g_E[2][BATCH];           // exact integer energies (x . y)
__device__ int g_finished;
__device__ int g_result;
__device__ int g_bad;                   // per-step convergence badness
__device__ int g_ckcount;               // check arrival counter

__device__ __forceinline__ int8_t sgn8(int v) {
    return (int8_t)((v > 0) - (v < 0));
}

// ----------------------------------------------------------------------------
__global__ void init_kernel(const int* __restrict__ max_iter) {
    int idx = blockIdx.x * blockDim.x + threadIdx.x;
    if (idx < 2 * BATCH) ((int*)g_E)[idx] = 0;
    if (idx == 0) {
        g_result = 0;
        g_bad = 0;
        g_ckcount = 0;
        g_finished = (*max_iter <= 0) ? 1 : 0;
    }
}

__global__ void cvt_w_kernel(const float* __restrict__ w) {
    int i = (blockIdx.x * blockDim.x + threadIdx.x) * 4;
    float4 v = *(const float4*)(w + i);
    char4 o;
    o.x = (int8_t)__float2int_rn(v.x);
    o.y = (int8_t)__float2int_rn(v.y);
    o.z = (int8_t)__float2int_rn(v.z);
    o.w = (int8_t)__float2int_rn(v.w);
    *(char4*)(g_w + i) = o;
}

__global__ void cvt_x_kernel(const float* __restrict__ x) {
    int i = (blockIdx.x * blockDim.x + threadIdx.x) * 4;
    float4 v = *(const float4*)(x + i);
    char4 o;
    o.x = (int8_t)__float2int_rn(v.x);
    o.y = (int8_t)__float2int_rn(v.y);
    o.z = (int8_t)__float2int_rn(v.z);
    o.w = (int8_t)__float2int_rn(v.w);
    *(char4*)(&g_x[0][0] + i) = o;
}

// ----------------------------------------------------------------------------
// Step kernel: fused s8 GEMM + sign + integer energy.
// grid = (NF/BN, BATCH/BM) = (8, 128) = 1024 CTAs, 256 threads.
// 8 warps as 2(M) x 4(N); each warp owns a 32x32 output tile.
// ----------------------------------------------------------------------------
__global__ __launch_bounds__(256) void step_kernel(int m, const int* __restrict__ max_iter) {
    if (g_finished || m > *max_iter) return;

    const int8_t* __restrict__ xcur = g_x[m % 3];
    int8_t* __restrict__ xnext = g_x[(m + 1) % 3];
    int* __restrict__ E = g_E[m & 1];

    extern __shared__ __align__(128) int8_t smem[];
    int8_t* As = smem;              // NSTG stages of BM*PR
    int8_t* Bs = smem + B_BASE;     // NSTG stages of BN*PR

    const int tid = threadIdx.x;
    const int lane = tid & 31, warp = tid >> 5;
    const int warpM = warp & 1, warpN = warp >> 1;   // 2 x 4 warps, 32x32 tiles
    const int rowBase = blockIdx.y * BM;
    const int colBase = blockIdx.x * BN;

    int acc[2][4][4];
#pragma unroll
    for (int a = 0; a < 2; a++)
#pragma unroll
        for (int b = 0; b < 4; b++)
#pragma unroll
            for (int c = 0; c < 4; c++) acc[a][b][c] = 0;

    const int ldRow = tid >> 2;            // 0..63
    const int ldOff = (tid & 3) * 16;      // 0/16/32/48
    auto loadStage = [&](int buf, int kt) {
        {
            uint32_t dst = (uint32_t)__cvta_generic_to_shared(
                &As[buf * A_STG + ldRow * PR + ldOff]);
            const int8_t* src = xcur + (size_t)(rowBase + ldRow) * NF + kt * BK + ldOff;
            asm volatile("cp.async.cg.shared.global [%0], [%1], 16;\n" :: "r"(dst), "l"(src));
        }
#pragma unroll
        for (int rep = 0; rep < 2; rep++) {
            int row = ldRow + rep * 64;
            uint32_t dst = (uint32_t)__cvta_generic_to_shared(
                &Bs[buf * B_STG + row * PR + ldOff]);
            // B = W^T = W (symmetric): rows are output cols, k contiguous.
            const int8_t* src = g_w + (size_t)(colBase + row) * NF + kt * BK + ldOff;
            asm volatile("cp.async.cg.shared.global [%0], [%1], 16;\n" :: "r"(dst), "l"(src));
        }
    };

#pragma unroll
    for (int s = 0; s < NSTG - 1; s++) {
        loadStage(s, s);
        asm volatile("cp.async.commit_group;\n");
    }

    const int lr8 = lane & 7;
    const int seg8 = (lane >> 3) & 1;
    const int kh16 = (lane >> 4) & 1;

    const int KT = NF / BK;  // 16
#pragma unroll 1
    for (int kt = 0; kt < KT; kt++) {
        int buf = kt & (NSTG - 1);
        asm volatile("cp.async.wait_group %0;\n" :: "n"(NSTG - 2));
        __syncthreads();

        int ktn = kt + NSTG - 1;
        if (ktn < KT) loadStage(ktn & (NSTG - 1), ktn);
        asm volatile("cp.async.commit_group;\n");   // empty commit ok: keeps alignment

#pragma unroll
        for (int ks = 0; ks < 2; ks++) {           // two k32 slices per BK=64
            const int kbyte = ks * 32;
            uint32_t af[2][4];
            uint32_t bf[2][4];
#pragma unroll
            for (int mi = 0; mi < 2; mi++) {
                int row = warpM * 32 + mi * 16 + lr8 + seg8 * 8;
                uint32_t addr = (uint32_t)__cvta_generic_to_shared(
                    &As[buf * A_STG + row * PR + kbyte + kh16 * 16]);
                asm volatile("ldmatrix.sync.aligned.m8n8.x4.shared.b16 {%0,%1,%2,%3}, [%4];"
                             : "=r"(af[mi][0]), "=r"(af[mi][1]), "=r"(af[mi][2]), "=r"(af[mi][3])
                             : "r"(addr));
            }
#pragma unroll
            for (int np = 0; np < 2; np++) {
                int row = warpN * 32 + np * 16 + lr8 + seg8 * 8;
                uint32_t addr = (uint32_t)__cvta_generic_to_shared(
                    &Bs[buf * B_STG + row * PR + kbyte + kh16 * 16]);
                asm volatile("ldmatrix.sync.aligned.m8n8.x4.shared.b16 {%0,%1,%2,%3}, [%4];"
                             : "=r"(bf[np][0]), "=r"(bf[np][1]), "=r"(bf[np][2]), "=r"(bf[np][3])
                             : "r"(addr));
            }
#pragma unroll
            for (int mi = 0; mi < 2; mi++)
#pragma unroll
                for (int ni = 0; ni < 4; ni++) {
                    int np = ni >> 1, lh = ni & 1;
                    asm volatile(
                        "mma.sync.aligned.m16n8k32.row.col.s32.s8.s8.s32 "
                        "{%0,%1,%2,%3}, {%4,%5,%6,%7}, {%8,%9}, {%0,%1,%2,%3};"
                        : "+r"(acc[mi][ni][0]), "+r"(acc[mi][ni][1]),
                          "+r"(acc[mi][ni][2]), "+r"(acc[mi][ni][3])
                        : "r"(af[mi][0]), "r"(af[mi][1]), "r"(af[mi][2]), "r"(af[mi][3]),
                          "r"(bf[np][lh]), "r"(bf[np][lh + 2]));
                }
        }
    }

    // ---- Fused epilogue: x_next = sign(y) (int8), E[row] += x_cur . y ----
    const int lr = lane >> 2, lc = lane & 3;
#pragma unroll
    for (int mi = 0; mi < 2; mi++) {
        int r0 = rowBase + warpM * 32 + mi * 16 + lr;
        int r1 = r0 + 8;
        int s0 = 0, s1 = 0;
#pragma unroll
        for (int ni = 0; ni < 4; ni++) {
            int c = colBase + warpN * 32 + ni * 8 + lc * 2;
            int v0 = acc[mi][ni][0], v1 = acc[mi][ni][1];
            int v2 = acc[mi][ni][2], v3 = acc[mi][ni][3];
            char2 xa = *(const char2*)(xcur + (size_t)r0 * NF + c);
            char2 xb = *(const char2*)(xcur + (size_t)r1 * NF + c);
            s0 += (int)xa.x * v0 + (int)xa.y * v1;
            s1 += (int)xb.x * v2 + (int)xb.y * v3;
            char2 o0; o0.x = sgn8(v0); o0.y = sgn8(v1);
            char2 o1; o1.x = sgn8(v2); o1.y = sgn8(v3);
            *(char2*)(xnext + (size_t)r0 * NF + c) = o0;
            *(char2*)(xnext + (size_t)r1 * NF + c) = o1;
        }
        s0 += __shfl_xor_sync(0xffffffffu, s0, 1);
        s0 += __shfl_xor_sync(0xffffffffu, s0, 2);
        s1 += __shfl_xor_sync(0xffffffffu, s1, 1);
        s1 += __shfl_xor_sync(0xffffffffu, s1, 2);
        if (lc == 0) {
            atomicAdd(&E[r0], s0);
            atomicAdd(&E[r1], s1);
        }
    }
}

// ----------------------------------------------------------------------------
// check(i): runs after step i+1. Exact integer-energy convergence test.
// grid = CKBLK blocks; block-OR -> atomicOr(g_bad); last arriving block
// decides and resets flags for the next step.
// ----------------------------------------------------------------------------
__global__ void check_kernel(int i, const int* __restrict__ max_iter) {
    int mit = *max_iter;
    if (g_finished || i >= mit) return;
    int* Ea = g_E[i & 1];
    const int* Eb = g_E[(i + 1) & 1];

    const int per = BATCH / CKBLK;             // 256 rows per block
    const int start = blockIdx.x * per;
    int bad = 0;
    for (int r = start + threadIdx.x; r < start + per; r += blockDim.x) {
        if (Ea[r] != Eb[r]) bad = 1;
        Ea[r] = 0;                             // recycle slot for step i+2
    }
    bad = __syncthreads_or(bad);
    if (threadIdx.x == 0) {
        if (bad) atomicOr(&g_bad, 1);
        __threadfence();
        int arrived = atomicAdd(&g_ckcount, 1);
        if (arrived == CKBLK - 1) {            // last block: decide
            int anybad = atomicAdd(&g_bad, 0);
            if (!anybad) {
                g_finished = 1;
                g_result = i % 3;              // converged: keep OLD x_i
            } else if (i == mit - 1) {
                g_finished = 1;
                g_result = (i + 1) % 3;        // iteration cap
            }
            g_bad = 0;                         // reset for next step
            g_ckcount = 0;
            __threadfence();
        }
    }
}

__global__ void out_kernel(float* __restrict__ out) {
    const int8_t* src = g_x[g_result];
    size_t i = ((size_t)blockIdx.x * blockDim.x + threadIdx.x) * 4;
    char4 v = *(const char4*)(src + i);
    float4 o;
    o.x = (float)v.x; o.y = (float)v.y; o.z = (float)v.z; o.w = (float)v.w;
    *(float4*)(out + i) = o;
}

// ----------------------------------------------------------------------------
extern "C" void kernel_launch(void* const* d_in, const int* in_sizes, int n_in,
                              void* d_out, int out_size) {
    const float* x = (const float*)d_in[0];
    const float* w = (const float*)d_in[1];
    const int* maxit = (const int*)d_in[2];
    float* out = (float*)d_out;

    cudaFuncSetAttribute(step_kernel, cudaFuncAttributeMaxDynamicSharedMemorySize,
                         SMEM_TOTAL);

    init_kernel<<<(2 * BATCH + 255) / 256, 256>>>(maxit);
    cvt_w_kernel<<<NF * NF / (256 * 4), 256>>>(w);
    cvt_x_kernel<<<BATCH * NF / (256 * 4), 256>>>(x);

    dim3 grid(NF / BN, BATCH / BM);  // (8, 128) = 1024 CTAs
    for (int mstep = 0; mstep <= 30; mstep++) {
        step_kernel<<<grid, 256, SMEM_TOTAL>>>(mstep, maxit);
        if (mstep >= 1) check_kernel<<<CKBLK, 256>>>(mstep - 1, maxit);
    }
    out_kernel<<<BATCH * NF / (4 * 256), 256>>>(out);
}